// round 2
// baseline (speedup 1.0000x reference)
#include <cuda_runtime.h>

#define N_NODES 8192
#define F_HID   128
#define ALPHA   0.2f
#define MAXE    32   // max edges per (row, 128-col tile); Bin(128,0.05) P(>=32) ~ 1e-13

// ---------------- scratch (device globals; no allocations allowed) ----------
__device__ float g_bufA[N_NODES * F_HID];
__device__ float g_bufB[N_NODES * F_HID];
__device__ float g_h  [N_NODES * F_HID];
__device__ float g_src[N_NODES];
__device__ float g_dst[N_NODES];
__device__ float g_m  [N_NODES];
__device__ float g_iz [N_NODES];

__device__ __forceinline__ float leaky(float x) { return x >= 0.f ? x : ALPHA * x; }

// ---------------------------------------------------------------------------
// GEMM: out[M,128] = act(A[M,K] @ W[K,128] + b),  M=8192, K in {256,128}
// block: 256 threads, 64 rows; thread computes 8 rows x 4 cols
// ---------------------------------------------------------------------------
__global__ void __launch_bounds__(256) gemm_kernel(
    const float* __restrict__ A, const float* __restrict__ W,
    const float* __restrict__ bias, float* __restrict__ out,
    int K, int do_relu)
{
    __shared__ float As[64][64];
    __shared__ float Ws[64][128];

    const int tid = threadIdx.x;
    const int tx = tid & 31;        // col group: cols 4*tx .. 4*tx+3
    const int ty = tid >> 5;        // row base: rows ty + 8*r
    const int row0 = blockIdx.x * 64;

    float acc[8][4];
#pragma unroll
    for (int r = 0; r < 8; r++)
#pragma unroll
        for (int c = 0; c < 4; c++) acc[r][c] = 0.f;

    for (int k0 = 0; k0 < K; k0 += 64) {
        // load A tile: 64x64 floats = 1024 float4, 4 per thread
#pragma unroll
        for (int i = 0; i < 4; i++) {
            int idx = tid + i * 256;
            int r = idx >> 4;
            int c = (idx & 15) << 2;
            float4 v = *reinterpret_cast<const float4*>(&A[(size_t)(row0 + r) * K + k0 + c]);
            *reinterpret_cast<float4*>(&As[r][c]) = v;
        }
        // load W tile: 64x128 floats = 2048 float4, 8 per thread
#pragma unroll
        for (int i = 0; i < 8; i++) {
            int idx = tid + i * 256;
            int r = idx >> 5;
            int c = (idx & 31) << 2;
            float4 v = *reinterpret_cast<const float4*>(&W[(size_t)(k0 + r) * 128 + c]);
            *reinterpret_cast<float4*>(&Ws[r][c]) = v;
        }
        __syncthreads();

#pragma unroll
        for (int k = 0; k < 64; k++) {
            float4 w = *reinterpret_cast<const float4*>(&Ws[k][tx << 2]);
#pragma unroll
            for (int r = 0; r < 8; r++) {
                float a = As[ty + (r << 3)][k];
                acc[r][0] = fmaf(a, w.x, acc[r][0]);
                acc[r][1] = fmaf(a, w.y, acc[r][1]);
                acc[r][2] = fmaf(a, w.z, acc[r][2]);
                acc[r][3] = fmaf(a, w.w, acc[r][3]);
            }
        }
        __syncthreads();
    }

    float4 bv = *reinterpret_cast<const float4*>(&bias[tx << 2]);
#pragma unroll
    for (int r = 0; r < 8; r++) {
        int row = row0 + ty + (r << 3);
        float4 o;
        o.x = acc[r][0] + bv.x;
        o.y = acc[r][1] + bv.y;
        o.z = acc[r][2] + bv.z;
        o.w = acc[r][3] + bv.w;
        if (do_relu) {
            o.x = fmaxf(o.x, 0.f); o.y = fmaxf(o.y, 0.f);
            o.z = fmaxf(o.z, 0.f); o.w = fmaxf(o.w, 0.f);
        }
        *reinterpret_cast<float4*>(&out[(size_t)row * 128 + (tx << 2)]) = o;
    }
}

// ---------------------------------------------------------------------------
// s_src = h @ a_w[0:128], s_dst = h @ a_w[128:256]   (one warp per row)
// ---------------------------------------------------------------------------
__global__ void __launch_bounds__(256) score_kernel(
    const float* __restrict__ h, const float* __restrict__ a_w,
    float* __restrict__ s_src, float* __restrict__ s_dst)
{
    int row = blockIdx.x * 8 + (threadIdx.x >> 5);
    int lane = threadIdx.x & 31;
    float4 hv = *reinterpret_cast<const float4*>(&h[(size_t)row * 128 + lane * 4]);
    float4 a1 = *reinterpret_cast<const float4*>(&a_w[lane * 4]);
    float4 a2 = *reinterpret_cast<const float4*>(&a_w[128 + lane * 4]);
    float d1 = hv.x * a1.x + hv.y * a1.y + hv.z * a1.z + hv.w * a1.w;
    float d2 = hv.x * a2.x + hv.y * a2.y + hv.z * a2.z + hv.w * a2.w;
#pragma unroll
    for (int o = 16; o; o >>= 1) {
        d1 += __shfl_xor_sync(0xffffffffu, d1, o);
        d2 += __shfl_xor_sync(0xffffffffu, d2, o);
    }
    if (lane == 0) { s_src[row] = d1; s_dst[row] = d2; }
}

// ---------------------------------------------------------------------------
// Pass 1: per-row masked softmax stats (max m, 1/Z). One warp per row.
// Streams adj once (256 MB) — HBM bound.
// ---------------------------------------------------------------------------
__global__ void __launch_bounds__(256) stats_kernel(
    const float* __restrict__ adj, const float* __restrict__ s_src,
    const float* __restrict__ s_dst, const float* __restrict__ p_ab,
    float* __restrict__ out_m, float* __restrict__ out_iz)
{
    const int row = blockIdx.x * 8 + (threadIdx.x >> 5);
    const int lane = threadIdx.x & 31;
    const float si = s_src[row];
    const float ab = *p_ab;
    const float4* arow = reinterpret_cast<const float4*>(adj + (size_t)row * N_NODES);
    const float4* trow = reinterpret_cast<const float4*>(s_dst);

    float m = -1e30f, z = 0.f;
#pragma unroll 4
    for (int it = 0; it < 64; it++) {
        int c4 = it * 32 + lane;
        float4 a = arow[c4];
        float4 t = trow[c4];
        float e;
        if (a.x >= 0.5f) { e = leaky(si + t.x + ab);
            if (e > m) { z = z * __expf(m - e) + 1.f; m = e; } else z += __expf(e - m); }
        if (a.y >= 0.5f) { e = leaky(si + t.y + ab);
            if (e > m) { z = z * __expf(m - e) + 1.f; m = e; } else z += __expf(e - m); }
        if (a.z >= 0.5f) { e = leaky(si + t.z + ab);
            if (e > m) { z = z * __expf(m - e) + 1.f; m = e; } else z += __expf(e - m); }
        if (a.w >= 0.5f) { e = leaky(si + t.w + ab);
            if (e > m) { z = z * __expf(m - e) + 1.f; m = e; } else z += __expf(e - m); }
    }
    // warp reduce (m, z)
#pragma unroll
    for (int o = 16; o; o >>= 1) {
        float mo = __shfl_xor_sync(0xffffffffu, m, o);
        float zo = __shfl_xor_sync(0xffffffffu, z, o);
        float mn = fmaxf(m, mo);
        z = z * __expf(m - mn) + zo * __expf(mo - mn);
        m = mn;
    }
    if (lane == 0) { out_m[row] = m; out_iz[row] = 1.f / z; }
}

// ---------------------------------------------------------------------------
// Pass 2: aggregation out = leaky(attention @ h)
// Block: 64 i-rows, 256 threads (4 threads/row, 32 cols each).
// Loops over 64 j-tiles of 128: h tile in smem (shared by all 64 rows),
// adj tile scanned once, edges compacted to smem lists, then FMA from smem.
// ---------------------------------------------------------------------------
#define AGG_SMEM (65536 + 512 + 256 + 256 + 256 + 256 + 8192 + 8192)

__global__ void __launch_bounds__(256) aggregate_kernel(
    const float* __restrict__ adj, const float* __restrict__ h,
    const float* __restrict__ s_src, const float* __restrict__ s_dst,
    const float* __restrict__ gm, const float* __restrict__ giz,
    const float* __restrict__ p_ab, float* __restrict__ out)
{
    extern __shared__ char smem_raw[];
    float (*hs)[128] = reinterpret_cast<float (*)[128]>(smem_raw);          // 64 KB
    float* ts   = reinterpret_cast<float*>(smem_raw + 65536);               // 512 B
    float* sis  = ts + 128;                                                 // 256 B
    float* mis  = sis + 64;                                                 // 256 B
    float* izs  = mis + 64;                                                 // 256 B
    int*   cnt  = reinterpret_cast<int*>(izs + 64);                         // 256 B
    float (*ew)[MAXE] = reinterpret_cast<float (*)[MAXE]>(cnt + 64);        // 8 KB
    int   (*ej)[MAXE] = reinterpret_cast<int (*)[MAXE]>(&ew[64][0]);        // 8 KB

    const int tid = threadIdx.x;
    const int i_loc = tid >> 2;     // 0..63
    const int q = tid & 3;          // col quarter: cols q*32..q*32+31
    const int r0 = blockIdx.x * 64;

    if (tid < 64) {
        sis[tid] = s_src[r0 + tid];
        mis[tid] = gm[r0 + tid];
        izs[tid] = giz[r0 + tid];
    }
    const float ab = *p_ab;

    float acc[32];
#pragma unroll
    for (int c = 0; c < 32; c++) acc[c] = 0.f;

    __syncthreads();
    const float si_ = sis[i_loc];
    const float mi_ = mis[i_loc];
    const float iz_ = izs[i_loc];
    const float* arow = adj + (size_t)(r0 + i_loc) * N_NODES;

    for (int jt = 0; jt < N_NODES; jt += 128) {
        __syncthreads();  // protect hs/lists from previous iteration's readers
        // load h tile: 128x128 floats = 4096 float4, 16 per thread
#pragma unroll
        for (int i = 0; i < 16; i++) {
            int idx = tid + i * 256;
            int r = idx >> 5;
            int c = (idx & 31) << 2;
            *reinterpret_cast<float4*>(&hs[r][c]) =
                *reinterpret_cast<const float4*>(&h[(size_t)(jt + r) * 128 + c]);
        }
        if (tid < 32)
            *reinterpret_cast<float4*>(&ts[tid * 4]) =
                *reinterpret_cast<const float4*>(&s_dst[jt + tid * 4]);
        if (q == 0) cnt[i_loc] = 0;
        __syncthreads();

        // phase A: scan 128 adj cols of my row (4 threads x 32 cols), compact edges
#pragma unroll
        for (int k = 0; k < 8; k++) {
            int jb = k * 16 + q * 4;
            float4 a = *reinterpret_cast<const float4*>(&arow[jt + jb]);
            if (a.x >= 0.5f) {
                float w = __expf(leaky(si_ + ts[jb + 0] + ab) - mi_) * iz_;
                int p = atomicAdd(&cnt[i_loc], 1);
                if (p < MAXE) { ew[i_loc][p] = w; ej[i_loc][p] = jb + 0; }
            }
            if (a.y >= 0.5f) {
                float w = __expf(leaky(si_ + ts[jb + 1] + ab) - mi_) * iz_;
                int p = atomicAdd(&cnt[i_loc], 1);
                if (p < MAXE) { ew[i_loc][p] = w; ej[i_loc][p] = jb + 1; }
            }
            if (a.z >= 0.5f) {
                float w = __expf(leaky(si_ + ts[jb + 2] + ab) - mi_) * iz_;
                int p = atomicAdd(&cnt[i_loc], 1);
                if (p < MAXE) { ew[i_loc][p] = w; ej[i_loc][p] = jb + 2; }
            }
            if (a.w >= 0.5f) {
                float w = __expf(leaky(si_ + ts[jb + 3] + ab) - mi_) * iz_;
                int p = atomicAdd(&cnt[i_loc], 1);
                if (p < MAXE) { ew[i_loc][p] = w; ej[i_loc][p] = jb + 3; }
            }
        }
        __syncthreads();

        // phase B: accumulate w * h[j][my 32 cols] from smem
        int n = cnt[i_loc];
        if (n > MAXE) n = MAXE;
        for (int p = 0; p < n; p++) {
            float w = ew[i_loc][p];
            const float* hrow = &hs[ej[i_loc][p]][q * 32];
#pragma unroll
            for (int c = 0; c < 8; c++) {
                float4 hv = *reinterpret_cast<const float4*>(&hrow[c * 4]);
                acc[c * 4 + 0] = fmaf(w, hv.x, acc[c * 4 + 0]);
                acc[c * 4 + 1] = fmaf(w, hv.y, acc[c * 4 + 1]);
                acc[c * 4 + 2] = fmaf(w, hv.z, acc[c * 4 + 2]);
                acc[c * 4 + 3] = fmaf(w, hv.w, acc[c * 4 + 3]);
            }
        }
    }

    // epilogue: out = leaky(acc)
    float* orow = out + (size_t)(r0 + i_loc) * 128 + q * 32;
#pragma unroll
    for (int c = 0; c < 8; c++) {
        float4 o;
        o.x = leaky(acc[c * 4 + 0]);
        o.y = leaky(acc[c * 4 + 1]);
        o.z = leaky(acc[c * 4 + 2]);
        o.w = leaky(acc[c * 4 + 3]);
        *reinterpret_cast<float4*>(&orow[c * 4]) = o;
    }
}

// ---------------------------------------------------------------------------
extern "C" void kernel_launch(void* const* d_in, const int* in_sizes, int n_in,
                              void* d_out, int out_size)
{
    const float* nodes = (const float*)d_in[0];
    const float* adj   = (const float*)d_in[1];
    const float* W1    = (const float*)d_in[2];
    const float* b1    = (const float*)d_in[3];
    const float* W2    = (const float*)d_in[4];
    const float* b2    = (const float*)d_in[5];
    const float* W3    = (const float*)d_in[6];
    const float* b3    = (const float*)d_in[7];
    const float* W4    = (const float*)d_in[8];
    const float* b4    = (const float*)d_in[9];
    const float* a_w   = (const float*)d_in[10];
    const float* a_b   = (const float*)d_in[11];
    float* out = (float*)d_out;

    float *pA, *pB, *pH, *pSrc, *pDst, *pM, *pIZ;
    cudaGetSymbolAddress((void**)&pA,  g_bufA);
    cudaGetSymbolAddress((void**)&pB,  g_bufB);
    cudaGetSymbolAddress((void**)&pH,  g_h);
    cudaGetSymbolAddress((void**)&pSrc, g_src);
    cudaGetSymbolAddress((void**)&pDst, g_dst);
    cudaGetSymbolAddress((void**)&pM,  g_m);
    cudaGetSymbolAddress((void**)&pIZ, g_iz);

    // 4-layer MLP
    gemm_kernel<<<128, 256>>>(nodes, W1, b1, pA, 256, 1);
    gemm_kernel<<<128, 256>>>(pA,    W2, b2, pB, 128, 1);
    gemm_kernel<<<128, 256>>>(pB,    W3, b3, pA, 128, 1);
    gemm_kernel<<<128, 256>>>(pA,    W4, b4, pH, 128, 0);

    // attention scores
    score_kernel<<<1024, 256>>>(pH, a_w, pSrc, pDst);

    // pass 1: softmax stats (streams adj)
    stats_kernel<<<1024, 256>>>(adj, pSrc, pDst, a_b, pM, pIZ);

    // pass 2: aggregation (streams adj again, h tiles in smem)
    cudaFuncSetAttribute(aggregate_kernel,
                         cudaFuncAttributeMaxDynamicSharedMemorySize, AGG_SMEM);
    aggregate_kernel<<<128, 256, AGG_SMEM>>>(adj, pH, pSrc, pDst, pM, pIZ, a_b, out);
}

// round 3
// speedup vs baseline: 2.6534x; 2.6534x over previous
#include <cuda_runtime.h>

#define N_NODES 8192
#define ALPHA   0.2f

// ---------------- scratch (device globals; no allocations allowed) ----------
__device__ float g_bufA[N_NODES * 128];
__device__ float g_bufB[N_NODES * 128];
__device__ float g_h  [N_NODES * 128];
__device__ float g_src[N_NODES];
__device__ float g_dst[N_NODES];
__device__ float g_zA [N_NODES];
__device__ float g_zB [N_NODES];
__device__ float g_gmax[1];

__device__ __forceinline__ float leaky(float x) { return x >= 0.f ? x : ALPHA * x; }

// ---------------------------------------------------------------------------
// GEMM: out[M,128] = act(A[M,K] @ W[K,128] + b), 32 rows/block, 256 blocks
// thread computes 4 rows x 4 cols
// ---------------------------------------------------------------------------
__global__ void __launch_bounds__(256) gemm_kernel(
    const float* __restrict__ A, const float* __restrict__ W,
    const float* __restrict__ bias, float* __restrict__ out,
    int K, int do_relu)
{
    __shared__ float As[32][64];
    __shared__ float Ws[64][128];

    const int tid = threadIdx.x;
    const int tx = tid & 31;        // cols 4*tx .. 4*tx+3
    const int ty = tid >> 5;        // rows ty + 8*r
    const int row0 = blockIdx.x * 32;

    float acc[4][4];
#pragma unroll
    for (int r = 0; r < 4; r++)
#pragma unroll
        for (int c = 0; c < 4; c++) acc[r][c] = 0.f;

    for (int k0 = 0; k0 < K; k0 += 64) {
        // A tile: 32x64 = 512 float4, 2 per thread
#pragma unroll
        for (int i = 0; i < 2; i++) {
            int idx = tid + i * 256;
            int r = idx >> 4;
            int c = (idx & 15) << 2;
            *reinterpret_cast<float4*>(&As[r][c]) =
                *reinterpret_cast<const float4*>(&A[(size_t)(row0 + r) * K + k0 + c]);
        }
        // W tile: 64x128 = 2048 float4, 8 per thread
#pragma unroll
        for (int i = 0; i < 8; i++) {
            int idx = tid + i * 256;
            int r = idx >> 5;
            int c = (idx & 31) << 2;
            *reinterpret_cast<float4*>(&Ws[r][c]) =
                *reinterpret_cast<const float4*>(&W[(size_t)(k0 + r) * 128 + c]);
        }
        __syncthreads();

#pragma unroll
        for (int k = 0; k < 64; k++) {
            float4 w = *reinterpret_cast<const float4*>(&Ws[k][tx << 2]);
#pragma unroll
            for (int r = 0; r < 4; r++) {
                float a = As[ty + (r << 3)][k];
                acc[r][0] = fmaf(a, w.x, acc[r][0]);
                acc[r][1] = fmaf(a, w.y, acc[r][1]);
                acc[r][2] = fmaf(a, w.z, acc[r][2]);
                acc[r][3] = fmaf(a, w.w, acc[r][3]);
            }
        }
        __syncthreads();
    }

    float4 bv = *reinterpret_cast<const float4*>(&bias[tx << 2]);
#pragma unroll
    for (int r = 0; r < 4; r++) {
        int row = row0 + ty + (r << 3);
        float4 o;
        o.x = acc[r][0] + bv.x;
        o.y = acc[r][1] + bv.y;
        o.z = acc[r][2] + bv.z;
        o.w = acc[r][3] + bv.w;
        if (do_relu) {
            o.x = fmaxf(o.x, 0.f); o.y = fmaxf(o.y, 0.f);
            o.z = fmaxf(o.z, 0.f); o.w = fmaxf(o.w, 0.f);
        }
        *reinterpret_cast<float4*>(&out[(size_t)row * 128 + (tx << 2)]) = o;
    }
}

// ---------------------------------------------------------------------------
// s_src = h @ a_w[0:128], s_dst = h @ a_w[128:256]   (one warp per row)
// ---------------------------------------------------------------------------
__global__ void __launch_bounds__(256) score_kernel(
    const float* __restrict__ h, const float* __restrict__ a_w,
    float* __restrict__ s_src, float* __restrict__ s_dst)
{
    int row = blockIdx.x * 8 + (threadIdx.x >> 5);
    int lane = threadIdx.x & 31;
    float4 hv = *reinterpret_cast<const float4*>(&h[(size_t)row * 128 + lane * 4]);
    float4 a1 = *reinterpret_cast<const float4*>(&a_w[lane * 4]);
    float4 a2 = *reinterpret_cast<const float4*>(&a_w[128 + lane * 4]);
    float d1 = hv.x * a1.x + hv.y * a1.y + hv.z * a1.z + hv.w * a1.w;
    float d2 = hv.x * a2.x + hv.y * a2.y + hv.z * a2.z + hv.w * a2.w;
#pragma unroll
    for (int o = 16; o; o >>= 1) {
        d1 += __shfl_xor_sync(0xffffffffu, d1, o);
        d2 += __shfl_xor_sync(0xffffffffu, d2, o);
    }
    if (lane == 0) { s_src[row] = d1; s_dst[row] = d2; }
}

// ---------------------------------------------------------------------------
// global max of s_dst -> g_gmax (for a safe softmax upper bound)
// ---------------------------------------------------------------------------
__global__ void __launch_bounds__(256) gmax_kernel(
    const float* __restrict__ s_dst, float* __restrict__ out)
{
    __shared__ float red[256];
    float m = -1e30f;
    for (int i = threadIdx.x; i < N_NODES; i += 256)
        m = fmaxf(m, s_dst[i]);
    red[threadIdx.x] = m;
    __syncthreads();
    for (int s = 128; s; s >>= 1) {
        if (threadIdx.x < s) red[threadIdx.x] = fmaxf(red[threadIdx.x], red[threadIdx.x + s]);
        __syncthreads();
    }
    if (threadIdx.x == 0) out[0] = red[0];
}

// ---------------------------------------------------------------------------
// Fused attention: single adj pass. Per row i with m_i = leaky(si + ab + gmax):
//   acc_i = sum_edges exp(e - m_i) * h_j,   z_i = sum_edges exp(e - m_i)
// Block: 64 rows x 8 threads/row (512 thr). Grid (2 j-halves x 128 row blocks)
// = 256 blocks -> single wave at 2 blocks/SM. Partial (acc, z) per half,
// combined by combine_kernel.
// Thread t of a row scans j-segment [t*16, t*16+16) of each 128-j tile and
// owns output cols {t*4 + 32k + c}. No atomics: per-thread edge lists,
// CAP = SEG = 16 so overflow is impossible.
// ---------------------------------------------------------------------------
#define RPB 64
#define TPR 8
#define JT  128
#define SEG 16
#define CAP 16

struct AttnSmem {
    float hs[JT][128];                 // 64 KB   h tile
    float ew[RPB][TPR][CAP];           // 32 KB   edge weights
    unsigned char ej[RPB][TPR][CAP];   //  8 KB   edge j (tile-local)
    int   cnt[RPB][TPR];               //  2 KB
    float ts[JT];                      // 512 B   s_dst tile
};

__global__ void __launch_bounds__(512, 2) attn_kernel(
    const float* __restrict__ adj, const float* __restrict__ h,
    const float* __restrict__ s_src, const float* __restrict__ s_dst,
    const float* __restrict__ p_ab, const float* __restrict__ p_gmax,
    float* __restrict__ accA, float* __restrict__ accB,
    float* __restrict__ zA, float* __restrict__ zB)
{
    extern __shared__ char smraw[];
    AttnSmem& s = *reinterpret_cast<AttnSmem*>(smraw);

    const int tid = threadIdx.x;
    const int row = tid >> 3;           // 0..63
    const int t   = tid & 7;            // 0..7
    const int r0  = blockIdx.y * RPB;
    const int half = blockIdx.x;
    const int j0  = half * (N_NODES / 2);
    float* accbuf = half ? accB : accA;
    float* zbuf   = half ? zB  : zA;

    const float ab   = *p_ab;
    const float gmax = *p_gmax;
    const float si   = s_src[r0 + row];
    const float mi   = leaky(si + ab + gmax);   // >= every e in this row

    float acc[16];
#pragma unroll
    for (int c = 0; c < 16; c++) acc[c] = 0.f;
    float z = 0.f;

    const float* arow = adj + (size_t)(r0 + row) * N_NODES + j0 + t * SEG;

    for (int jt = 0; jt < N_NODES / 2; jt += JT) {
        __syncthreads();   // prev iteration's readers done with hs/lists
        // h tile: 128x128 = 4096 float4, 8 per thread
#pragma unroll
        for (int i = 0; i < 8; i++) {
            int idx = tid + i * 512;
            int r = idx >> 5;
            int c = (idx & 31) << 2;
            *reinterpret_cast<float4*>(&s.hs[r][c]) =
                *reinterpret_cast<const float4*>(&h[(size_t)(j0 + jt + r) * 128 + c]);
        }
        if (tid < 32)
            *reinterpret_cast<float4*>(&s.ts[tid * 4]) =
                *reinterpret_cast<const float4*>(&s_dst[j0 + jt + tid * 4]);
        __syncthreads();

        // phase A: scan my 16-j segment, build edge list (exp once per edge)
        int c_ = 0;
#pragma unroll
        for (int u = 0; u < 4; u++) {
            float4 a = *reinterpret_cast<const float4*>(arow + jt + u * 4);
            int jb = t * SEG + u * 4;
            if (a.x >= 0.5f) { s.ew[row][t][c_] = __expf(leaky(si + s.ts[jb + 0] + ab) - mi);
                               s.ej[row][t][c_] = (unsigned char)(jb + 0); c_++; }
            if (a.y >= 0.5f) { s.ew[row][t][c_] = __expf(leaky(si + s.ts[jb + 1] + ab) - mi);
                               s.ej[row][t][c_] = (unsigned char)(jb + 1); c_++; }
            if (a.z >= 0.5f) { s.ew[row][t][c_] = __expf(leaky(si + s.ts[jb + 2] + ab) - mi);
                               s.ej[row][t][c_] = (unsigned char)(jb + 2); c_++; }
            if (a.w >= 0.5f) { s.ew[row][t][c_] = __expf(leaky(si + s.ts[jb + 3] + ab) - mi);
                               s.ej[row][t][c_] = (unsigned char)(jb + 3); c_++; }
        }
        s.cnt[row][t] = c_;
        __syncthreads();

        // phase B: all 8 threads of the row walk all its edges
#pragma unroll 1
        for (int sg = 0; sg < TPR; sg++) {
            int n = s.cnt[row][sg];
            for (int p = 0; p < n; p++) {
                float w = s.ew[row][sg][p];        // smem broadcast
                int   j = s.ej[row][sg][p];
                z += w;
                const float* hr = s.hs[j];
#pragma unroll
                for (int k = 0; k < 4; k++) {
                    float4 hv = *reinterpret_cast<const float4*>(&hr[t * 4 + 32 * k]);
                    acc[k * 4 + 0] = fmaf(w, hv.x, acc[k * 4 + 0]);
                    acc[k * 4 + 1] = fmaf(w, hv.y, acc[k * 4 + 1]);
                    acc[k * 4 + 2] = fmaf(w, hv.z, acc[k * 4 + 2]);
                    acc[k * 4 + 3] = fmaf(w, hv.w, acc[k * 4 + 3]);
                }
            }
        }
    }

    const size_t ro = (size_t)(r0 + row) * 128;
#pragma unroll
    for (int k = 0; k < 4; k++) {
        float4 o;
        o.x = acc[k * 4 + 0]; o.y = acc[k * 4 + 1];
        o.z = acc[k * 4 + 2]; o.w = acc[k * 4 + 3];
        *reinterpret_cast<float4*>(&accbuf[ro + t * 4 + 32 * k]) = o;
    }
    if (t == 0) zbuf[r0 + row] = z;
}

// ---------------------------------------------------------------------------
// out = leaky((accA + accB) / (zA + zB))
// ---------------------------------------------------------------------------
__global__ void __launch_bounds__(256) combine_kernel(
    const float* __restrict__ a, const float* __restrict__ b,
    const float* __restrict__ za, const float* __restrict__ zb,
    float* __restrict__ out)
{
    int idx = blockIdx.x * 256 + threadIdx.x;   // float4 index
    int row = idx >> 5;                          // 32 float4 per row
    float inv = 1.f / (za[row] + zb[row]);
    float4 x = reinterpret_cast<const float4*>(a)[idx];
    float4 y = reinterpret_cast<const float4*>(b)[idx];
    float4 o;
    o.x = leaky((x.x + y.x) * inv);
    o.y = leaky((x.y + y.y) * inv);
    o.z = leaky((x.z + y.z) * inv);
    o.w = leaky((x.w + y.w) * inv);
    reinterpret_cast<float4*>(out)[idx] = o;
}

// ---------------------------------------------------------------------------
extern "C" void kernel_launch(void* const* d_in, const int* in_sizes, int n_in,
                              void* d_out, int out_size)
{
    const float* nodes = (const float*)d_in[0];
    const float* adj   = (const float*)d_in[1];
    const float* W1    = (const float*)d_in[2];
    const float* b1    = (const float*)d_in[3];
    const float* W2    = (const float*)d_in[4];
    const float* b2    = (const float*)d_in[5];
    const float* W3    = (const float*)d_in[6];
    const float* b3    = (const float*)d_in[7];
    const float* W4    = (const float*)d_in[8];
    const float* b4    = (const float*)d_in[9];
    const float* a_w   = (const float*)d_in[10];
    const float* a_b   = (const float*)d_in[11];
    float* out = (float*)d_out;

    float *pA, *pB, *pH, *pSrc, *pDst, *pZA, *pZB, *pGM;
    cudaGetSymbolAddress((void**)&pA,  g_bufA);
    cudaGetSymbolAddress((void**)&pB,  g_bufB);
    cudaGetSymbolAddress((void**)&pH,  g_h);
    cudaGetSymbolAddress((void**)&pSrc, g_src);
    cudaGetSymbolAddress((void**)&pDst, g_dst);
    cudaGetSymbolAddress((void**)&pZA, g_zA);
    cudaGetSymbolAddress((void**)&pZB, g_zB);
    cudaGetSymbolAddress((void**)&pGM, g_gmax);

    // 4-layer MLP
    gemm_kernel<<<256, 256>>>(nodes, W1, b1, pA, 256, 1);
    gemm_kernel<<<256, 256>>>(pA,    W2, b2, pB, 128, 1);
    gemm_kernel<<<256, 256>>>(pB,    W3, b3, pA, 128, 1);
    gemm_kernel<<<256, 256>>>(pA,    W4, b4, pH, 128, 0);

    // attention scores + global max bound
    score_kernel<<<1024, 256>>>(pH, a_w, pSrc, pDst);
    gmax_kernel<<<1, 256>>>(pDst, pGM);

    // fused single-pass attention (unnormalized) over adj
    static int smem_set = 0;
    if (!smem_set) {
        cudaFuncSetAttribute(attn_kernel,
                             cudaFuncAttributeMaxDynamicSharedMemorySize,
                             (int)sizeof(AttnSmem));
        smem_set = 1;
    }
    dim3 agrid(2, 128);
    attn_kernel<<<agrid, 512, sizeof(AttnSmem)>>>(
        adj, pH, pSrc, pDst, a_b, pGM, pA, pB, pZA, pZB);

    // normalize + activation
    combine_kernel<<<1024, 256>>>(pA, pB, pZA, pZB, out);
}

// round 4
// speedup vs baseline: 3.3380x; 1.2580x over previous
#include <cuda_runtime.h>
#include <cstdint>

#define N_NODES 8192
#define ALPHA   0.2f

// ---------------- scratch (device globals; no allocations allowed) ----------
__device__ float g_bufA[N_NODES * 128];
__device__ float g_bufB[N_NODES * 128];
__device__ float g_h  [N_NODES * 128];
__device__ float g_src[N_NODES];
__device__ float g_dst[N_NODES];
__device__ float g_zA [N_NODES];
__device__ float g_zB [N_NODES];
__device__ float g_gmax[1];

__device__ __forceinline__ float leaky(float x) { return x >= 0.f ? x : ALPHA * x; }

__device__ __forceinline__ unsigned long long pack2(float a, float b) {
    unsigned long long r;
    asm("mov.b64 %0, {%1, %2};" : "=l"(r)
        : "r"(__float_as_uint(a)), "r"(__float_as_uint(b)));
    return r;
}
__device__ __forceinline__ void unpack2(unsigned long long d, float& a, float& b) {
    unsigned x, y;
    asm("mov.b64 {%0, %1}, %2;" : "=r"(x), "=r"(y) : "l"(d));
    a = __uint_as_float(x); b = __uint_as_float(y);
}
__device__ __forceinline__ void fma2(unsigned long long& d,
                                     unsigned long long a, unsigned long long b) {
    asm("fma.rn.f32x2 %0, %1, %2, %0;" : "+l"(d) : "l"(a), "l"(b));
}
__device__ __forceinline__ void cpa16(unsigned dst, const void* src) {
    asm volatile("cp.async.ca.shared.global [%0], [%1], 16;"
                 :: "r"(dst), "l"(src));
}
__device__ __forceinline__ void cpa_commit() {
    asm volatile("cp.async.commit_group;" ::: "memory");
}
__device__ __forceinline__ void cpa_wait0() {
    asm volatile("cp.async.wait_group 0;" ::: "memory");
}

// ---------------------------------------------------------------------------
// GEMM: out[M,128] = act(A[M,K] @ W[K,128] + b). 32 rows/block, 256 blocks.
// Thread: 4 rows (2 row-pairs) x 4 cols, f32x2 FMA. A tile stored transposed
// so row pairs load as a single b64 (warp-broadcast).
// ---------------------------------------------------------------------------
__global__ void __launch_bounds__(256, 4) gemm_kernel(
    const float* __restrict__ A, const float* __restrict__ W,
    const float* __restrict__ bias, float* __restrict__ out,
    int K, int do_relu)
{
    __shared__ float At[64][34];     // transposed A tile [k][row], pad 34 (8B-aligned pairs)
    __shared__ float Ws[64][128];

    const int tid = threadIdx.x;
    const int tx = tid & 31;         // cols 4*tx..4*tx+3
    const int ty = tid >> 5;         // rows ty*4..ty*4+3
    const int row0 = blockIdx.x * 32;

    unsigned long long acc[2][4];
#pragma unroll
    for (int u = 0; u < 2; u++)
#pragma unroll
        for (int c = 0; c < 4; c++) acc[u][c] = 0ull;

    for (int k0 = 0; k0 < K; k0 += 64) {
        // A tile 32x64 -> transposed store
#pragma unroll
        for (int i = 0; i < 2; i++) {
            int idx = tid + i * 256;
            int r = idx >> 4;
            int c = (idx & 15) << 2;
            float4 v = *reinterpret_cast<const float4*>(&A[(size_t)(row0 + r) * K + k0 + c]);
            At[c + 0][r] = v.x; At[c + 1][r] = v.y;
            At[c + 2][r] = v.z; At[c + 3][r] = v.w;
        }
        // W tile 64x128
#pragma unroll
        for (int i = 0; i < 8; i++) {
            int idx = tid + i * 256;
            int r = idx >> 5;
            int c = (idx & 31) << 2;
            *reinterpret_cast<float4*>(&Ws[r][c]) =
                *reinterpret_cast<const float4*>(&W[(size_t)(k0 + r) * 128 + c]);
        }
        __syncthreads();

#pragma unroll 8
        for (int k = 0; k < 64; k++) {
            unsigned long long a01 =
                *reinterpret_cast<const unsigned long long*>(&At[k][ty * 4]);
            unsigned long long a23 =
                *reinterpret_cast<const unsigned long long*>(&At[k][ty * 4 + 2]);
            float4 w = *reinterpret_cast<const float4*>(&Ws[k][tx << 2]);
            unsigned long long w0 = pack2(w.x, w.x);
            unsigned long long w1 = pack2(w.y, w.y);
            unsigned long long w2 = pack2(w.z, w.z);
            unsigned long long w3 = pack2(w.w, w.w);
            fma2(acc[0][0], a01, w0); fma2(acc[0][1], a01, w1);
            fma2(acc[0][2], a01, w2); fma2(acc[0][3], a01, w3);
            fma2(acc[1][0], a23, w0); fma2(acc[1][1], a23, w1);
            fma2(acc[1][2], a23, w2); fma2(acc[1][3], a23, w3);
        }
        __syncthreads();
    }

    float4 bv = *reinterpret_cast<const float4*>(&bias[tx << 2]);
#pragma unroll
    for (int u = 0; u < 2; u++) {
        float lo0, hi0, lo1, hi1, lo2, hi2, lo3, hi3;
        unpack2(acc[u][0], lo0, hi0);
        unpack2(acc[u][1], lo1, hi1);
        unpack2(acc[u][2], lo2, hi2);
        unpack2(acc[u][3], lo3, hi3);
        float4 olo, ohi;
        olo.x = lo0 + bv.x; olo.y = lo1 + bv.y; olo.z = lo2 + bv.z; olo.w = lo3 + bv.w;
        ohi.x = hi0 + bv.x; ohi.y = hi1 + bv.y; ohi.z = hi2 + bv.z; ohi.w = hi3 + bv.w;
        if (do_relu) {
            olo.x = fmaxf(olo.x, 0.f); olo.y = fmaxf(olo.y, 0.f);
            olo.z = fmaxf(olo.z, 0.f); olo.w = fmaxf(olo.w, 0.f);
            ohi.x = fmaxf(ohi.x, 0.f); ohi.y = fmaxf(ohi.y, 0.f);
            ohi.z = fmaxf(ohi.z, 0.f); ohi.w = fmaxf(ohi.w, 0.f);
        }
        int rlo = row0 + ty * 4 + 2 * u;
        *reinterpret_cast<float4*>(&out[(size_t)rlo * 128 + (tx << 2)]) = olo;
        *reinterpret_cast<float4*>(&out[(size_t)(rlo + 1) * 128 + (tx << 2)]) = ohi;
    }
}

// ---------------------------------------------------------------------------
// s_src = h @ a_w[0:128], s_dst = h @ a_w[128:256]   (one warp per row)
// ---------------------------------------------------------------------------
__global__ void __launch_bounds__(256) score_kernel(
    const float* __restrict__ h, const float* __restrict__ a_w,
    float* __restrict__ s_src, float* __restrict__ s_dst)
{
    int row = blockIdx.x * 8 + (threadIdx.x >> 5);
    int lane = threadIdx.x & 31;
    float4 hv = *reinterpret_cast<const float4*>(&h[(size_t)row * 128 + lane * 4]);
    float4 a1 = *reinterpret_cast<const float4*>(&a_w[lane * 4]);
    float4 a2 = *reinterpret_cast<const float4*>(&a_w[128 + lane * 4]);
    float d1 = hv.x * a1.x + hv.y * a1.y + hv.z * a1.z + hv.w * a1.w;
    float d2 = hv.x * a2.x + hv.y * a2.y + hv.z * a2.z + hv.w * a2.w;
#pragma unroll
    for (int o = 16; o; o >>= 1) {
        d1 += __shfl_xor_sync(0xffffffffu, d1, o);
        d2 += __shfl_xor_sync(0xffffffffu, d2, o);
    }
    if (lane == 0) { s_src[row] = d1; s_dst[row] = d2; }
}

__global__ void __launch_bounds__(256) gmax_kernel(
    const float* __restrict__ s_dst, float* __restrict__ out)
{
    __shared__ float red[256];
    float m = -1e30f;
    for (int i = threadIdx.x; i < N_NODES; i += 256)
        m = fmaxf(m, s_dst[i]);
    red[threadIdx.x] = m;
    __syncthreads();
    for (int s = 128; s; s >>= 1) {
        if (threadIdx.x < s) red[threadIdx.x] = fmaxf(red[threadIdx.x], red[threadIdx.x + s]);
        __syncthreads();
    }
    if (threadIdx.x == 0) out[0] = red[0];
}

// ---------------------------------------------------------------------------
// Fused attention, software-pipelined:
//   per tile: [cp.async h(k+1); LDG adj(k+1)] || phaseB(k) ; bar ; phaseA(k+1)
// Block: 64 rows x 8 threads/row (512 thr), j-tile 64, double-buffered tiles
// and per-row edge lists (ballot-compacted, no atomics).
// ---------------------------------------------------------------------------
#define JT2  64
#define NT   64          // tiles per half (4096/64)
#define RPB  64
#define CAP  24

struct AttnSmem {
    float hs[2][JT2][128];             // 64 KB
    float ew[2][RPB][CAP];             // 12 KB
    float ts[2][JT2];                  // 512 B
    int   cnt[2][RPB];                 // 512 B
    unsigned char ej[2][RPB][CAP];     // 3 KB
};

__global__ void __launch_bounds__(512, 2) attn_kernel(
    const float* __restrict__ adj, const float* __restrict__ h,
    const float* __restrict__ s_src, const float* __restrict__ s_dst,
    const float* __restrict__ p_ab, const float* __restrict__ p_gmax,
    float* __restrict__ accA, float* __restrict__ accB,
    float* __restrict__ zA, float* __restrict__ zB)
{
    extern __shared__ char smraw[];
    AttnSmem& s = *reinterpret_cast<AttnSmem*>(smraw);

    const int tid = threadIdx.x;
    const int row = tid >> 3;            // 0..63
    const int t   = tid & 7;             // 0..7
    const int r0  = blockIdx.y * RPB;
    const int half = blockIdx.x;
    const int j0  = half * (N_NODES / 2);
    float* accbuf = half ? accB : accA;
    float* zbuf   = half ? zB  : zA;

    const float ab   = *p_ab;
    const float gmax = *p_gmax;
    const float si   = s_src[r0 + row];
    const float mi   = leaky(si + ab + gmax);

    const unsigned sm_base = (unsigned)__cvta_generic_to_shared(&s);
    const unsigned hs_u0 = sm_base;                         // hs[0]
    const unsigned hs_u1 = sm_base + JT2 * 128 * 4;         // hs[1]
    const unsigned ts_u0 = sm_base + 2 * JT2 * 128 * 4 + 2 * RPB * CAP * 4;
    const unsigned ts_u1 = ts_u0 + JT2 * 4;

    unsigned long long acc[8];
#pragma unroll
    for (int i = 0; i < 8; i++) acc[i] = 0ull;
    float z = 0.f;

    const float* arow = adj + (size_t)(r0 + row) * N_NODES + j0;

    // ---- tile loader via cp.async (h + s_dst slices) ----
    auto load_tile = [&](int tile, int b) {
        unsigned hdst = (b ? hs_u1 : hs_u0);
#pragma unroll
        for (int i = 0; i < 4; i++) {
            int idx = tid + i * 512;
            int r = idx >> 5;
            int c = (idx & 31) << 2;
            cpa16(hdst + (unsigned)(r * 128 + c) * 4,
                  &h[(size_t)(j0 + tile * JT2 + r) * 128 + c]);
        }
        if (tid < 16)
            cpa16((b ? ts_u1 : ts_u0) + tid * 16, &s_dst[j0 + tile * JT2 + tid * 4]);
    };

    // ---- phase A: ballot-compacted per-row edge list for tile -> buffer b ----
    auto phaseA = [&](int b, float4 a0, float4 a1) {
        unsigned m = 0;
        if (a0.x >= 0.5f) m |= 1u;
        if (a0.y >= 0.5f) m |= 2u;
        if (a0.z >= 0.5f) m |= 4u;
        if (a0.w >= 0.5f) m |= 8u;
        if (a1.x >= 0.5f) m |= 16u;
        if (a1.y >= 0.5f) m |= 32u;
        if (a1.z >= 0.5f) m |= 64u;
        if (a1.w >= 0.5f) m |= 128u;
        int c = __popc(m);
        int pre = c;
#pragma unroll
        for (int o = 1; o < 8; o <<= 1) {
            int v = __shfl_up_sync(0xffffffffu, pre, o, 8);
            if (t >= o) pre += v;
        }
        int base = pre - c;
        if (t == 7) s.cnt[b][row] = pre;
        const float* tsb = s.ts[b];
        while (m) {
            int bb = __ffs(m) - 1;
            m &= m - 1;
            int j = t * 8 + bb;
            if (base < CAP) {
                s.ew[b][row][base] = __expf(leaky(si + tsb[j] + ab) - mi);
                s.ej[b][row][base] = (unsigned char)j;
            }
            base++;
        }
    };

    // ---- phase B: accumulate this row's edges from buffer b ----
    auto phaseB = [&](int b) {
        int n = s.cnt[b][row];
        if (n > CAP) n = CAP;
        const float* ewp = s.ew[b][row];
        const unsigned char* ejp = s.ej[b][row];
        const unsigned hb = (b ? hs_u1 : hs_u0) + t * 16;
        for (int p = 0; p < n; p++) {
            float w = ewp[p];
            int j = ejp[p];
            z += w;
            unsigned long long w2 = pack2(w, w);
            unsigned ad = hb + (unsigned)j * 512;
            unsigned long long p0, p1, p2, p3, p4, p5, p6, p7;
            asm("ld.shared.v2.b64 {%0,%1}, [%2];" : "=l"(p0), "=l"(p1) : "r"(ad));
            asm("ld.shared.v2.b64 {%0,%1}, [%2];" : "=l"(p2), "=l"(p3) : "r"(ad + 128));
            asm("ld.shared.v2.b64 {%0,%1}, [%2];" : "=l"(p4), "=l"(p5) : "r"(ad + 256));
            asm("ld.shared.v2.b64 {%0,%1}, [%2];" : "=l"(p6), "=l"(p7) : "r"(ad + 384));
            fma2(acc[0], p0, w2); fma2(acc[1], p1, w2);
            fma2(acc[2], p2, w2); fma2(acc[3], p3, w2);
            fma2(acc[4], p4, w2); fma2(acc[5], p5, w2);
            fma2(acc[6], p6, w2); fma2(acc[7], p7, w2);
        }
    };

    // ---- prologue: tile 0 ----
    load_tile(0, 0);
    cpa_commit();
    float4 pa0 = *reinterpret_cast<const float4*>(arow + t * 8);
    float4 pa1 = *reinterpret_cast<const float4*>(arow + t * 8 + 4);
    cpa_wait0();
    __syncthreads();
    phaseA(0, pa0, pa1);
    __syncwarp();

    // ---- main pipelined loop ----
    for (int k = 0; k < NT; k++) {
        int buf = k & 1, nb = buf ^ 1;
        bool more = (k + 1 < NT);
        float4 na0, na1;
        if (more) {
            load_tile(k + 1, nb);
            cpa_commit();
            na0 = *reinterpret_cast<const float4*>(arow + (k + 1) * JT2 + t * 8);
            na1 = *reinterpret_cast<const float4*>(arow + (k + 1) * JT2 + t * 8 + 4);
        }
        phaseB(buf);
        if (more) {
            cpa_wait0();
            __syncthreads();
            phaseA(nb, na0, na1);
            __syncwarp();
        }
    }

    // ---- epilogue ----
    const size_t ro = (size_t)(r0 + row) * 128;
#pragma unroll
    for (int kk = 0; kk < 4; kk++) {
        float4 o;
        unpack2(acc[2 * kk], o.x, o.y);
        unpack2(acc[2 * kk + 1], o.z, o.w);
        *reinterpret_cast<float4*>(&accbuf[ro + t * 4 + 32 * kk]) = o;
    }
    if (t == 0) zbuf[r0 + row] = z;
}

// ---------------------------------------------------------------------------
// out = leaky((accA + accB) / (zA + zB))
// ---------------------------------------------------------------------------
__global__ void __launch_bounds__(256) combine_kernel(
    const float* __restrict__ a, const float* __restrict__ b,
    const float* __restrict__ za, const float* __restrict__ zb,
    float* __restrict__ out)
{
    int idx = blockIdx.x * 256 + threadIdx.x;
    int row = idx >> 5;
    float inv = 1.f / (za[row] + zb[row]);
    float4 x = reinterpret_cast<const float4*>(a)[idx];
    float4 y = reinterpret_cast<const float4*>(b)[idx];
    float4 o;
    o.x = leaky((x.x + y.x) * inv);
    o.y = leaky((x.y + y.y) * inv);
    o.z = leaky((x.z + y.z) * inv);
    o.w = leaky((x.w + y.w) * inv);
    reinterpret_cast<float4*>(out)[idx] = o;
}

// ---------------------------------------------------------------------------
extern "C" void kernel_launch(void* const* d_in, const int* in_sizes, int n_in,
                              void* d_out, int out_size)
{
    const float* nodes = (const float*)d_in[0];
    const float* adj   = (const float*)d_in[1];
    const float* W1    = (const float*)d_in[2];
    const float* b1    = (const float*)d_in[3];
    const float* W2    = (const float*)d_in[4];
    const float* b2    = (const float*)d_in[5];
    const float* W3    = (const float*)d_in[6];
    const float* b3    = (const float*)d_in[7];
    const float* W4    = (const float*)d_in[8];
    const float* b4    = (const float*)d_in[9];
    const float* a_w   = (const float*)d_in[10];
    const float* a_b   = (const float*)d_in[11];
    float* out = (float*)d_out;

    float *pA, *pB, *pH, *pSrc, *pDst, *pZA, *pZB, *pGM;
    cudaGetSymbolAddress((void**)&pA,  g_bufA);
    cudaGetSymbolAddress((void**)&pB,  g_bufB);
    cudaGetSymbolAddress((void**)&pH,  g_h);
    cudaGetSymbolAddress((void**)&pSrc, g_src);
    cudaGetSymbolAddress((void**)&pDst, g_dst);
    cudaGetSymbolAddress((void**)&pZA, g_zA);
    cudaGetSymbolAddress((void**)&pZB, g_zB);
    cudaGetSymbolAddress((void**)&pGM, g_gmax);

    // 4-layer MLP
    gemm_kernel<<<256, 256>>>(nodes, W1, b1, pA, 256, 1);
    gemm_kernel<<<256, 256>>>(pA,    W2, b2, pB, 128, 1);
    gemm_kernel<<<256, 256>>>(pB,    W3, b3, pA, 128, 1);
    gemm_kernel<<<256, 256>>>(pA,    W4, b4, pH, 128, 0);

    // attention scores + global max bound
    score_kernel<<<1024, 256>>>(pH, a_w, pSrc, pDst);
    gmax_kernel<<<1, 256>>>(pDst, pGM);

    // fused single-pass attention over adj (pipelined)
    cudaFuncSetAttribute(attn_kernel,
                         cudaFuncAttributeMaxDynamicSharedMemorySize,
                         (int)sizeof(AttnSmem));
    dim3 agrid(2, 128);
    attn_kernel<<<agrid, 512, sizeof(AttnSmem)>>>(
        adj, pH, pSrc, pDst, a_b, pGM, pA, pB, pZA, pZB);

    // normalize + activation
    combine_kernel<<<1024, 256>>>(pA, pB, pZA, pZB, out);
}